// round 7
// baseline (speedup 1.0000x reference)
#include <cuda_runtime.h>
#include <cuda_bf16.h>
#include <cstdint>

// out[b,s] = | prod_k cos((x[b,k]-sv[s,k])/2) |  =  | P12 * P34 |
// P12 = 1/2 [ cos((u+ - v+)/2) + cos((u- - v-)/2) ],  u± = x0±x1, v± = s0±s1
// -> each P is a 4-term dot product of row features vs col features.
// Output path: STS.128 into double-buffered smem staging, drained by 1D
// cp.async.bulk (TMA) shared->global -- removes the STG.128 LSU issue cost.
#define NB 4096
#define NS 4096

__device__ __forceinline__ uint64_t mul2(uint64_t a, uint64_t b) {
    uint64_t r; asm("mul.rn.f32x2 %0, %1, %2;" : "=l"(r) : "l"(a), "l"(b)); return r;
}
__device__ __forceinline__ uint64_t fma2(uint64_t a, uint64_t b, uint64_t c) {
    uint64_t r; asm("fma.rn.f32x2 %0, %1, %2, %3;" : "=l"(r) : "l"(a), "l"(b), "l"(c)); return r;
}
__device__ __forceinline__ uint64_t abs2(uint64_t v) {
    asm("and.b64 %0, %0, 0x7FFFFFFF7FFFFFFF;" : "+l"(v)); return v;
}
__device__ __forceinline__ uint64_t dup2(float v) {
    uint64_t r; asm("mov.b64 %0, {%1, %1};" : "=l"(r) : "f"(v)); return r;
}
__device__ __forceinline__ uint32_t s2u(const void* p) {
    uint32_t a;
    asm("{ .reg .u64 t; cvta.to.shared.u64 t, %1; cvt.u32.u64 %0, t; }"
        : "=r"(a) : "l"(p));
    return a;
}

// Block: 64 rows x 256 cols, 4 chunks of 16 rows. Thread: 4 cols x 16 rows.
__global__ __launch_bounds__(256, 4) void qk_tma_kernel(
    const float* __restrict__ x,
    const float* __restrict__ sv,
    float* __restrict__ out)
{
    // A (row) features: 4 groups of (c dup, s dup) per row, 1/2 folded in.
    __shared__ __align__(16) float sxf[64 * 16];          // 4 KB
    // B (col) features, f-major: {C+12,S+12,C-12,S-12,C+34,S+34,C-34,S-34}
    __shared__ __align__(16) float sbf[8 * 256];          // 8 KB
    // Output staging: 2 buffers x 16 rows x 256 cols
    __shared__ __align__(16) float stg[2][16 * 256];      // 32 KB

    const int b0 = blockIdx.y << 6;
    const int s0 = blockIdx.x << 8;
    const int t  = threadIdx.x;

    // ---- A fill: one sincos/thread (t = row*4 + g) ----
    {
        const int g = t & 3;
        float v = x[b0 * 4 + t];
        float p = __shfl_xor_sync(0xFFFFFFFFu, v, 1);
        float u = (g & 1) ? (p - v) : (v + p);
        float sn, cs;
        __sincosf(u * 0.5f, &sn, &cs);
        cs *= 0.5f; sn *= 0.5f;
        uint64_t* rec = reinterpret_cast<uint64_t*>(sxf) + ((t >> 2) << 3) + (g << 1);
        rec[0] = dup2(cs);
        rec[1] = dup2(sn);
    }
    // ---- B fill: one col per thread ----
    {
        float4 v = *reinterpret_cast<const float4*>(&sv[(size_t)(s0 + t) * 4]);
        float sn, cs;
        __sincosf((v.x + v.y) * 0.5f, &sn, &cs); sbf[0*256 + t] = cs; sbf[1*256 + t] = sn;
        __sincosf((v.x - v.y) * 0.5f, &sn, &cs); sbf[2*256 + t] = cs; sbf[3*256 + t] = sn;
        __sincosf((v.z + v.w) * 0.5f, &sn, &cs); sbf[4*256 + t] = cs; sbf[5*256 + t] = sn;
        __sincosf((v.z - v.w) * 0.5f, &sn, &cs); sbf[6*256 + t] = cs; sbf[7*256 + t] = sn;
    }
    __syncthreads();

    const int cg = t & 63;    // 4 cols at s0 + 4*cg
    const int rq = t >> 6;    // 0..3, warp-uniform

    // ---- hoist B features (8 coalesced LDS.128) ----
    ulonglong2 B[8];
#pragma unroll
    for (int f = 0; f < 8; f++)
        B[f] = *reinterpret_cast<const ulonglong2*>(&sbf[f * 256 + (cg << 2)]);

    const uint32_t stg0 = s2u(&stg[0][0]);
    const uint32_t stg1 = s2u(&stg[1][0]);

#pragma unroll
    for (int c = 0; c < 4; c++) {
        // gate staging-buffer reuse on the TMA *read* of its previous contents
        if (c >= 2) {
            if (t == 0)
                asm volatile("cp.async.bulk.wait_group.read 1;" ::: "memory");
            __syncthreads();
        }
        float* buf = stg[c & 1];

        // ---- compute 16 rows (4 per thread, strided by 4) ----
#pragma unroll
        for (int i = 0; i < 4; i++) {
            const int r   = rq + (i << 2);        // row within chunk, warp-uniform
            const int row = (c << 4) + r;         // row within block tile
            const ulonglong2* arec =
                reinterpret_cast<const ulonglong2*>(&sxf[row << 4]);  // broadcast
            ulonglong2 q0 = arec[0], q1 = arec[1], q2 = arec[2], q3 = arec[3];

            uint64_t p12a = fma2(q1.y, B[3].x, fma2(q1.x, B[2].x,
                            fma2(q0.y, B[1].x, mul2(q0.x, B[0].x))));
            uint64_t p34a = fma2(q3.y, B[7].x, fma2(q3.x, B[6].x,
                            fma2(q2.y, B[5].x, mul2(q2.x, B[4].x))));
            uint64_t p12b = fma2(q1.y, B[3].y, fma2(q1.x, B[2].y,
                            fma2(q0.y, B[1].y, mul2(q0.x, B[0].y))));
            uint64_t p34b = fma2(q3.y, B[7].y, fma2(q3.x, B[6].y,
                            fma2(q2.y, B[5].y, mul2(q2.x, B[4].y))));

            ulonglong2 o;
            o.x = abs2(mul2(p12a, p34a));
            o.y = abs2(mul2(p12b, p34b));
            *reinterpret_cast<ulonglong2*>(&buf[(r << 8) + (cg << 2)]) = o;  // STS.128
        }
        __syncthreads();

        // ---- drain chunk via 1D bulk copies (thread 0): 16 rows x 1 KB ----
        if (t == 0) {
            asm volatile("fence.proxy.async.shared::cta;" ::: "memory");
            const uint32_t sbase = (c & 1) ? stg1 : stg0;
            float* gbase = out + (size_t)(b0 + (c << 4)) * NS + s0;
#pragma unroll
            for (int rr = 0; rr < 16; rr++) {
                asm volatile(
                    "cp.async.bulk.global.shared::cta.bulk_group [%0], [%1], %2;"
                    :: "l"(gbase + (size_t)rr * NS), "r"(sbase + rr * 1024),
                       "r"(1024) : "memory");
            }
            asm volatile("cp.async.bulk.commit_group;" ::: "memory");
        }
    }

    // ensure all bulk stores are fully done before kernel exit
    if (t == 0)
        asm volatile("cp.async.bulk.wait_group 0;" ::: "memory");
}

extern "C" void kernel_launch(void* const* d_in, const int* in_sizes, int n_in,
                              void* d_out, int out_size) {
    const float* x  = (const float*)d_in[0];
    const float* sv = (const float*)d_in[1];
    float* out = (float*)d_out;

    dim3 grid(NS / 256, NB / 64);   // 16 x 64 = 1024 blocks
    qk_tma_kernel<<<grid, 256>>>(x, sv, out);
}